// round 9
// baseline (speedup 1.0000x reference)
#include <cuda_runtime.h>

#define N_NODES 50000
#define IN_F    128
#define OUT_F   64
#define HEADS   2
#define ALPHA   0.2f

__device__ float  g_v[512];          // [which(i/j)][head][128]
__device__ float2 g_si[N_NODES];
__device__ float2 g_sj[N_NODES];
__device__ float2 g_c[N_NODES];      // per-node sum of exp(e) per head
__device__ float  g_Z[2];            // global softmax denominator per head

// ---------------------------------------------------------------------------
// 1) v = W @ a (both halves, both heads); also zero g_Z
__global__ void prep_v_kernel(const float* __restrict__ W,
                              const float* __restrict__ a) {
    int t = threadIdx.x;            // 512 threads
    if (t < 2) g_Z[t] = 0.0f;
    int which = t >> 8;
    int h     = (t >> 7) & 1;
    int i     = t & 127;
    const float* wrow = W + h * (IN_F * OUT_F) + i * OUT_F;
    const float* av   = a + h * (2 * OUT_F) + which * OUT_F;
    float s = 0.f;
#pragma unroll 16
    for (int o = 0; o < OUT_F; o++) s += wrow[o] * av[o];
    g_v[which * 256 + h * 128 + i] = s;
}

// ---------------------------------------------------------------------------
// 2) per-node scores (one warp per node); also zeroes g_c
__global__ void __launch_bounds__(256) node_s_kernel(const float* __restrict__ x, int N) {
    __shared__ float vsm[512];
    int tid = threadIdx.x;
    vsm[tid]       = g_v[tid];
    vsm[tid + 256] = g_v[tid + 256];
    __syncthreads();

    int warp = tid >> 5, lane = tid & 31;
    int n = blockIdx.x * 8 + warp;
    if (n >= N) return;

    float4 xv = ((const float4*)x)[(size_t)n * 32 + lane];
    const float4* v4 = (const float4*)vsm;
    float4 vi0 = v4[lane];
    float4 vi1 = v4[32 + lane];
    float4 vj0 = v4[64 + lane];
    float4 vj1 = v4[96 + lane];

    float si0 = xv.x*vi0.x + xv.y*vi0.y + xv.z*vi0.z + xv.w*vi0.w;
    float si1 = xv.x*vi1.x + xv.y*vi1.y + xv.z*vi1.z + xv.w*vi1.w;
    float sj0 = xv.x*vj0.x + xv.y*vj0.y + xv.z*vj0.z + xv.w*vj0.w;
    float sj1 = xv.x*vj1.x + xv.y*vj1.y + xv.z*vj1.z + xv.w*vj1.w;

#pragma unroll
    for (int off = 16; off; off >>= 1) {
        si0 += __shfl_xor_sync(0xffffffffu, si0, off);
        si1 += __shfl_xor_sync(0xffffffffu, si1, off);
        sj0 += __shfl_xor_sync(0xffffffffu, sj0, off);
        sj1 += __shfl_xor_sync(0xffffffffu, sj1, off);
    }
    if (lane == 0) {
        g_si[n] = make_float2(si0, si1);
        g_sj[n] = make_float2(sj0, sj1);
        g_c[n]  = make_float2(0.f, 0.f);
    }
}

// ---------------------------------------------------------------------------
// 3) edge pass + fused global-Z reduction (frozen: measured)
__global__ void __launch_bounds__(256) edge_kernel(const int* __restrict__ ei, int E) {
    int k = blockIdx.x * blockDim.x + threadIdx.x;
    float z0 = 0.f, z1 = 0.f;
    if (k < E) {
        int src = __ldg(ei + k);
        int dst = __ldg(ei + E + k);
        float2 si = g_si[src];
        float2 sj = g_sj[dst];
        float e0 = si.x + sj.x;
        float e1 = si.y + sj.y;
        e0 = e0 > 0.f ? e0 : ALPHA * e0;
        e1 = e1 > 0.f ? e1 : ALPHA * e1;
        z0 = __expf(e0);
        z1 = __expf(e1);
        asm volatile("red.global.add.v2.f32 [%0], {%1, %2};"
                     :: "l"(&g_c[dst]), "f"(z0), "f"(z1) : "memory");
    }
#pragma unroll
    for (int off = 16; off; off >>= 1) {
        z0 += __shfl_xor_sync(0xffffffffu, z0, off);
        z1 += __shfl_xor_sync(0xffffffffu, z1, off);
    }
    __shared__ float s0[8], s1[8];
    int warp = threadIdx.x >> 5, lane = threadIdx.x & 31;
    if (lane == 0) { s0[warp] = z0; s1[warp] = z1; }
    __syncthreads();
    if (threadIdx.x == 0) {
        float t0 = 0.f, t1 = 0.f;
#pragma unroll
        for (int w = 0; w < 8; w++) { t0 += s0[w]; t1 += s1[w]; }
        asm volatile("red.global.add.v2.f32 [%0], {%1, %2};"
                     :: "l"(g_Z), "f"(t0), "f"(t1) : "memory");
    }
}

// ---------------------------------------------------------------------------
// 4) out = (x @ W) * c/Z -- tf32 mma.sync, PERSISTENT + cp.async DOUBLE BUFFER.
//    xs kept as raw f32 (cp.async 16B, no register roundtrip); A fragments
//    are cvt.rna.tf32'd in the mainloop (fma/alu pipes are idle).
//    ws staged once, tf32, TRANSPOSED ws[c][k] (conflict-free, measured).
#define XS_STRIDE 132
#define TILE_M    128

__device__ __forceinline__ unsigned f2tf32(float f) {
    unsigned u;
    asm("cvt.rna.tf32.f32 %0, %1;" : "=r"(u) : "f"(f));
    return u;
}

__device__ __forceinline__ void mma_tf32(float* d,
                                         unsigned a0, unsigned a1, unsigned a2, unsigned a3,
                                         unsigned b0, unsigned b1) {
    asm volatile("mma.sync.aligned.m16n8k8.row.col.f32.tf32.tf32.f32 "
                 "{%0,%1,%2,%3}, {%4,%5,%6,%7}, {%8,%9}, {%0,%1,%2,%3};"
                 : "+f"(d[0]), "+f"(d[1]), "+f"(d[2]), "+f"(d[3])
                 : "r"(a0), "r"(a1), "r"(a2), "r"(a3), "r"(b0), "r"(b1));
}

// prefetch one 128-row x tile into xs buffer via cp.async (16B per op)
__device__ __forceinline__ void prefetch_tile(unsigned xs_base_sa, const float* x,
                                              int n0, int N, int tid) {
#pragma unroll
    for (int it = 0; it < 16; it++) {
        int idx = tid + it * 256;        // 0..4095
        int r   = idx >> 5;
        int k4  = idx & 31;
        int n   = n0 + r;
        unsigned sa = xs_base_sa + (r * XS_STRIDE + k4 * 4) * 4;
        const float* ga = x + ((size_t)(n < N ? n : 0) * 128 + k4 * 4);
        int zfill = (n < N) ? 16 : 0;
        asm volatile("cp.async.ca.shared.global [%0], [%1], 16, %2;"
                     :: "r"(sa), "l"(ga), "r"(zfill) : "memory");
    }
    asm volatile("cp.async.commit_group;" ::: "memory");
}

__global__ void __launch_bounds__(256, 1) out_gemm_kernel(const float* __restrict__ x,
                                                          const float* __restrict__ W,
                                                          float* __restrict__ out,
                                                          int N, int numTiles) {
    extern __shared__ unsigned smem[];
    // xs0 [128][132] f32 | xs1 [128][132] f32 | ws [128][132] tf32 (ws[c][k])
    unsigned* ws = smem + 2 * TILE_M * XS_STRIDE;

    int tid = threadIdx.x;
    unsigned smem_sa = (unsigned)__cvta_generic_to_shared(smem);
    unsigned xs_sa[2] = {smem_sa, smem_sa + TILE_M * XS_STRIDE * 4};

    // stage W once: W[h][i][o] -> ws[(h*64+o)*XS + i]
    for (int idx = tid; idx < HEADS * IN_F * OUT_F; idx += 256) {
        int h = idx >> 13;
        int i = (idx >> 6) & 127;
        int o = idx & 63;
        ws[(h * 64 + o) * XS_STRIDE + i] = f2tf32(W[idx]);
    }

    int wid  = tid >> 5, lane = tid & 31;
    int wm   = wid >> 1;            // 0..3 : 32-row band
    int wn   = wid & 1;             // 0..1 : 64-col band (== head)
    int g    = lane >> 2;           // groupID
    int t    = lane & 3;            // threadID_in_group
    int cb   = wn * 64;
    float rz = 1.0f / g_Z[wn];

    int tile0 = blockIdx.x;
    if (tile0 < numTiles)
        prefetch_tile(xs_sa[0], x, tile0 * TILE_M, N, tid);
    else
        asm volatile("cp.async.commit_group;" ::: "memory");

    int buf = 0;
    for (int tile = tile0; tile < numTiles; tile += gridDim.x) {
        int n0 = tile * TILE_M;
        // issue prefetch for the NEXT tile into the other buffer
        int nxt = tile + gridDim.x;
        if (nxt < numTiles)
            prefetch_tile(xs_sa[buf ^ 1], x, nxt * TILE_M, N, tid);
        else
            asm volatile("cp.async.commit_group;" ::: "memory");

        // wait for current tile's group (<=1 pending = newest still in flight)
        asm volatile("cp.async.wait_group 1;" ::: "memory");
        __syncthreads();

        const unsigned* xs = (const unsigned*)smem + (size_t)buf * TILE_M * XS_STRIDE;

        float acc[2][8][4];
#pragma unroll
        for (int mi = 0; mi < 2; mi++)
#pragma unroll
            for (int ni = 0; ni < 8; ni++)
#pragma unroll
                for (int q = 0; q < 4; q++) acc[mi][ni][q] = 0.f;

#pragma unroll 4
        for (int ks = 0; ks < 16; ks++) {
            int k0 = ks * 8;
            unsigned av[2][4];
#pragma unroll
            for (int mi = 0; mi < 2; mi++) {
                int r0 = wm * 32 + mi * 16;
                av[mi][0] = f2tf32(__uint_as_float(xs[(r0 + g)     * XS_STRIDE + k0 + t]));
                av[mi][1] = f2tf32(__uint_as_float(xs[(r0 + g + 8) * XS_STRIDE + k0 + t]));
                av[mi][2] = f2tf32(__uint_as_float(xs[(r0 + g)     * XS_STRIDE + k0 + t + 4]));
                av[mi][3] = f2tf32(__uint_as_float(xs[(r0 + g + 8) * XS_STRIDE + k0 + t + 4]));
            }
            unsigned bv[8][2];
#pragma unroll
            for (int ni = 0; ni < 8; ni++) {
                int c = cb + ni * 8 + g;
                bv[ni][0] = ws[c * XS_STRIDE + k0 + t];
                bv[ni][1] = ws[c * XS_STRIDE + k0 + t + 4];
            }
#pragma unroll
            for (int mi = 0; mi < 2; mi++)
#pragma unroll
                for (int ni = 0; ni < 8; ni++)
                    mma_tf32(acc[mi][ni], av[mi][0], av[mi][1], av[mi][2], av[mi][3],
                             bv[ni][0], bv[ni][1]);
        }
        __syncthreads();   // all reads of xs[buf] done before it becomes a prefetch target

        // epilogue: scale by c[n,head]/Z_head; head == wn
#pragma unroll
        for (int mi = 0; mi < 2; mi++) {
            int r0 = n0 + wm * 32 + mi * 16 + g;   // rows for c0,c1
            int r1 = r0 + 8;                        // rows for c2,c3
            float scl0 = 0.f, scl1 = 0.f;
            if (r0 < N) {
                float2 cc = g_c[r0];
                scl0 = (wn ? cc.y : cc.x) * rz;
            }
            if (r1 < N) {
                float2 cc = g_c[r1];
                scl1 = (wn ? cc.y : cc.x) * rz;
            }
#pragma unroll
            for (int ni = 0; ni < 8; ni++) {
                int col = cb + ni * 8 + 2 * t;
                if (r0 < N)
                    *(float2*)&out[(size_t)r0 * 128 + col] =
                        make_float2(acc[mi][ni][0] * scl0, acc[mi][ni][1] * scl0);
                if (r1 < N)
                    *(float2*)&out[(size_t)r1 * 128 + col] =
                        make_float2(acc[mi][ni][2] * scl1, acc[mi][ni][3] * scl1);
            }
        }
        buf ^= 1;
    }
}

// ---------------------------------------------------------------------------
extern "C" void kernel_launch(void* const* d_in, const int* in_sizes, int n_in,
                              void* d_out, int out_size) {
    const float* x  = (const float*)d_in[0];
    const float* W  = (const float*)d_in[1];
    const float* a  = (const float*)d_in[2];
    const int*   ei = (const int*)d_in[3];
    float* out = (float*)d_out;

    int N = in_sizes[0] / IN_F;
    if (N > N_NODES) N = N_NODES;
    int E = in_sizes[3] / 2;
    int numTiles = (N + TILE_M - 1) / TILE_M;

    prep_v_kernel<<<1, 512>>>(W, a);
    node_s_kernel<<<(N + 7) / 8, 256>>>(x, N);
    edge_kernel<<<(E + 255) / 256, 256>>>(ei, E);

    const int smem_bytes = 3 * TILE_M * XS_STRIDE * 4;  // ~198KB
    cudaFuncSetAttribute(out_gemm_kernel,
                         cudaFuncAttributeMaxDynamicSharedMemorySize, smem_bytes);
    int grid = numTiles < 148 ? numTiles : 148;
    out_gemm_kernel<<<grid, 256, smem_bytes>>>(x, W, out, N, numTiles);
}